// round 1
// baseline (speedup 1.0000x reference)
#include <cuda_runtime.h>
#include <cstdint>

#define DIMN   256
#define BATCH  8
#define SEQ    4096
#define LRC    0.1f
#define DECAYC 0.9f
#define MTOT   (BATCH*SEQ)          // 32768

// ---------------- scratch (device globals: allocation-free) ----------------
__device__ float g_k[BATCH*SEQ*DIMN];   // eta-scaled k
__device__ float g_v[BATCH*SEQ*DIMN];
__device__ float g_q[BATCH*SEQ*DIMN];
__device__ float g_y[BATCH*SEQ*DIMN];   // memory_out

// ---------------- packed f32x2 helpers (Blackwell FFMA2) -------------------
typedef unsigned long long ull;

__device__ __forceinline__ ull pack2(float lo, float hi) {
    ull r; asm("mov.b64 %0,{%1,%2};" : "=l"(r) : "f"(lo), "f"(hi)); return r;
}
__device__ __forceinline__ void unpack2(ull p, float& lo, float& hi) {
    asm("mov.b64 {%0,%1},%2;" : "=f"(lo), "=f"(hi) : "l"(p));
}
__device__ __forceinline__ ull fma2(ull a, ull b, ull c) {
    ull d; asm("fma.rn.f32x2 %0,%1,%2,%3;" : "=l"(d) : "l"(a), "l"(b), "l"(c)); return d;
}
__device__ __forceinline__ ull mul2(ull a, ull b) {
    ull d; asm("mul.rn.f32x2 %0,%1,%2;" : "=l"(d) : "l"(a), "l"(b)); return d;
}

// ---------------- GEMM: C = alpha * (X @ W^T + bias) -----------------------
// X: (MTOT, 256) row-major, W: (256, 256) row-major, C: (MTOT, 256)
// mode: 0 -> C=g_k, 1 -> C=g_v, 2 -> C=g_q, 3 -> X=g_y, C=Cout
#define BM 128
#define BN 64
#define BK 16

__global__ __launch_bounds__(256, 2) void gemm_kernel(
    const float* __restrict__ Xin, const float* __restrict__ W,
    const float* __restrict__ bias, float* __restrict__ Cout,
    float alpha, int mode)
{
    const float* X = (mode == 3) ? g_y : Xin;
    float* C = (mode == 0) ? g_k : (mode == 1) ? g_v : (mode == 2) ? g_q : Cout;

    __shared__ __align__(16) float Xs[BK][BM];
    __shared__ __align__(16) float Ws[BK][BN];

    const int tid   = threadIdx.x;
    const int mBase = blockIdx.x * BM;
    const int nBase = blockIdx.y * BN;

    const int tx = tid & 15;        // n-group
    const int ty = tid >> 4;        // m-group
    const int m0 = ty * 8;
    const int n0 = tx * 4;

    // accumulators: row-pairs (packed) x 4 cols
    ull acc[4][4];
#pragma unroll
    for (int i = 0; i < 4; i++)
#pragma unroll
        for (int j = 0; j < 4; j++) acc[i][j] = 0ull;   // (+0.0f, +0.0f)

    const int xrow = tid & 127;
    const int xkq  = tid >> 7;      // 0..1
    const int wrow = tid & 63;
    const int wkq  = tid >> 6;      // 0..3

    for (int k0 = 0; k0 < DIMN; k0 += BK) {
        // issue global loads first (hide latency across the barrier)
        float4 xv0 = *(const float4*)(X + (size_t)(mBase + xrow) * DIMN + k0 + xkq * 4);
        float4 xv1 = *(const float4*)(X + (size_t)(mBase + xrow) * DIMN + k0 + (xkq + 2) * 4);
        float4 wv  = *(const float4*)(W + (size_t)(nBase + wrow) * DIMN + k0 + wkq * 4);

        __syncthreads();   // previous tile's compute done before overwrite
        Xs[xkq * 4 + 0][xrow] = xv0.x;
        Xs[xkq * 4 + 1][xrow] = xv0.y;
        Xs[xkq * 4 + 2][xrow] = xv0.z;
        Xs[xkq * 4 + 3][xrow] = xv0.w;
        Xs[(xkq + 2) * 4 + 0][xrow] = xv1.x;
        Xs[(xkq + 2) * 4 + 1][xrow] = xv1.y;
        Xs[(xkq + 2) * 4 + 2][xrow] = xv1.z;
        Xs[(xkq + 2) * 4 + 3][xrow] = xv1.w;
        Ws[wkq * 4 + 0][wrow] = wv.x;
        Ws[wkq * 4 + 1][wrow] = wv.y;
        Ws[wkq * 4 + 2][wrow] = wv.z;
        Ws[wkq * 4 + 3][wrow] = wv.w;
        __syncthreads();

#pragma unroll
        for (int kk = 0; kk < BK; kk++) {
            ulonglong2 A0 = *(const ulonglong2*)&Xs[kk][m0];      // rows m0..m0+3 (2 pairs)
            ulonglong2 A1 = *(const ulonglong2*)&Xs[kk][m0 + 4];  // rows m0+4..m0+7
            float4 bv = *(const float4*)&Ws[kk][n0];
            ull ap[4] = { A0.x, A0.y, A1.x, A1.y };
            ull bp[4] = { pack2(bv.x, bv.x), pack2(bv.y, bv.y),
                          pack2(bv.z, bv.z), pack2(bv.w, bv.w) };
#pragma unroll
            for (int i = 0; i < 4; i++)
#pragma unroll
                for (int j = 0; j < 4; j++)
                    acc[i][j] = fma2(ap[i], bp[j], acc[i][j]);
        }
    }

    // epilogue: out = alpha * (acc + bias)
    float4 bb = *(const float4*)(bias + nBase + n0);
    float bia[4] = { bb.x, bb.y, bb.z, bb.w };
#pragma unroll
    for (int i = 0; i < 4; i++) {
        float lo[4], hi[4];
#pragma unroll
        for (int j = 0; j < 4; j++) unpack2(acc[i][j], lo[j], hi[j]);
        float4 r0 = make_float4(alpha * (lo[0] + bia[0]), alpha * (lo[1] + bia[1]),
                                alpha * (lo[2] + bia[2]), alpha * (lo[3] + bia[3]));
        float4 r1 = make_float4(alpha * (hi[0] + bia[0]), alpha * (hi[1] + bia[1]),
                                alpha * (hi[2] + bia[2]), alpha * (hi[3] + bia[3]));
        *(float4*)(C + (size_t)(mBase + m0 + 2 * i)     * DIMN + nBase + n0) = r0;
        *(float4*)(C + (size_t)(mBase + m0 + 2 * i + 1) * DIMN + nBase + n0) = r1;
    }
}

// ---------------- sequential Hebbian scan ----------------------------------
// grid: BATCH*16 CTAs (one wave). CTA = (batch b, 16-column slice js).
// warp w (0..7) owns columns jj = js*16 + 2w, jj+1; lane owns rows lane*8..+7.
// State A[i][j] lives in registers as 4 packed row-pairs x 2 columns.
__global__ __launch_bounds__(256, 1) void scan_kernel(
    const float* __restrict__ state_in, float* __restrict__ state_out)
{
    const int b    = blockIdx.x >> 4;
    const int js   = blockIdx.x & 15;
    const int warp = threadIdx.x >> 5;
    const int lane = threadIdx.x & 31;
    const int jj   = js * 16 + warp * 2;
    const int i0   = lane * 8;

    // init A from input state
    ull a[4][2];
#pragma unroll
    for (int r = 0; r < 4; r++) {
        const float* sp = state_in + ((size_t)b * DIMN + i0 + 2 * r) * DIMN + jj;
        a[r][0] = pack2(sp[0], sp[DIMN]);         // rows (i0+2r, i0+2r+1), col jj
        a[r][1] = pack2(sp[1], sp[DIMN + 1]);     // col jj+1
    }

    const ull decayp = pack2(DECAYC, DECAYC);
    const size_t base = (size_t)b * SEQ * DIMN;
    const float* kbase = g_k + base + i0;
    const float* qbase = g_q + base + i0;
    const float* vbase = g_v + base + jj;
    float*       ybase = g_y + base + jj;

    // prefetch t = 0
    ulonglong2 k01 = *(const ulonglong2*)(kbase);
    ulonglong2 k23 = *(const ulonglong2*)(kbase + 4);
    ulonglong2 q01 = *(const ulonglong2*)(qbase);
    ulonglong2 q23 = *(const ulonglong2*)(qbase + 4);
    float2 vv = *(const float2*)(vbase);

#pragma unroll 2
    for (int t = 0; t < SEQ; ++t) {
        const int tn = (t + 1 < SEQ) ? (t + 1) : (SEQ - 1);
        // prefetch next step while computing current
        ulonglong2 nk01 = *(const ulonglong2*)(kbase + (size_t)tn * DIMN);
        ulonglong2 nk23 = *(const ulonglong2*)(kbase + (size_t)tn * DIMN + 4);
        ulonglong2 nq01 = *(const ulonglong2*)(qbase + (size_t)tn * DIMN);
        ulonglong2 nq23 = *(const ulonglong2*)(qbase + (size_t)tn * DIMN + 4);
        float2 nvv = *(const float2*)(vbase + (size_t)tn * DIMN);

        const ull c0 = pack2(vv.x, vv.x);
        const ull c1 = pack2(vv.y, vv.y);
        ull kp[4] = { k01.x, k01.y, k23.x, k23.y };
        ull qp[4] = { q01.x, q01.y, q23.x, q23.y };
        ull acc0 = 0ull, acc1 = 0ull;
#pragma unroll
        for (int r = 0; r < 4; r++) {
            a[r][0] = fma2(decayp, a[r][0], mul2(kp[r], c0));  // A = lam*A + k'*v
            acc0    = fma2(qp[r],  a[r][0], acc0);             // y += q*A (post-update)
            a[r][1] = fma2(decayp, a[r][1], mul2(kp[r], c1));
            acc1    = fma2(qp[r],  a[r][1], acc1);
        }
        float y0a, y0b, y1a, y1b;
        unpack2(acc0, y0a, y0b);
        unpack2(acc1, y1a, y1b);
        float y0 = y0a + y0b;
        float y1 = y1a + y1b;
#pragma unroll
        for (int off = 16; off > 0; off >>= 1) {
            y0 += __shfl_xor_sync(0xffffffffu, y0, off);
            y1 += __shfl_xor_sync(0xffffffffu, y1, off);
        }
        if (lane == 0) *(float2*)(ybase + (size_t)t * DIMN) = make_float2(y0, y1);

        k01 = nk01; k23 = nk23; q01 = nq01; q23 = nq23; vv = nvv;
    }

    if (state_out) {
#pragma unroll
        for (int r = 0; r < 4; r++) {
            float lo0, hi0, lo1, hi1;
            unpack2(a[r][0], lo0, hi0);
            unpack2(a[r][1], lo1, hi1);
            float* sp = state_out + ((size_t)b * DIMN + i0 + 2 * r) * DIMN + jj;
            sp[0] = lo0; sp[1] = lo1;
            sp[DIMN] = hi0; sp[DIMN + 1] = hi1;
        }
    }
}

// ---------------- launch ---------------------------------------------------
extern "C" void kernel_launch(void* const* d_in, const int* in_sizes, int n_in,
                              void* d_out, int out_size)
{
    const float* x  = (const float*)d_in[0];
    const float* st = (const float*)d_in[1];
    const float* Wk = (const float*)d_in[2];
    const float* bk = (const float*)d_in[3];
    const float* Wv = (const float*)d_in[4];
    const float* bv = (const float*)d_in[5];
    const float* Wq = (const float*)d_in[6];
    const float* bq = (const float*)d_in[7];
    const float* Wo = (const float*)d_in[8];
    const float* bo = (const float*)d_in[9];

    float* out = (float*)d_out;
    float* state_out = nullptr;
    const long long need = (long long)BATCH * SEQ * DIMN + (long long)BATCH * DIMN * DIMN;
    if ((long long)out_size >= need)
        state_out = out + (size_t)BATCH * SEQ * DIMN;

    dim3 grid(MTOT / BM, DIMN / BN);   // (256, 4)

    // projections (k is pre-scaled by eta = LR, including its bias)
    gemm_kernel<<<grid, 256>>>(x, Wk, bk, nullptr, LRC, 0);
    gemm_kernel<<<grid, 256>>>(x, Wv, bv, nullptr, 1.0f, 1);
    gemm_kernel<<<grid, 256>>>(x, Wq, bq, nullptr, 1.0f, 2);

    // recurrent scan (one wave: 128 CTAs)
    scan_kernel<<<BATCH * 16, 256>>>(st, state_out);

    // output projection
    gemm_kernel<<<grid, 256>>>(nullptr, Wo, bo, out, 1.0f, 3);
}

// round 2
// speedup vs baseline: 2.3356x; 2.3356x over previous
#include <cuda_runtime.h>
#include <cstdint>
#include <math.h>

#define DIMN   256
#define BATCH  8
#define SEQ    4096
#define LRC    0.1f
#define DECAYC 0.9f
#define MTOT   (BATCH*SEQ)          // 32768
#define CH     64                   // chunk length
#define NC     (SEQ/CH)             // 64 chunks

// ---------------- scratch (device globals: allocation-free) ----------------
__device__ float g_k[BATCH*SEQ*DIMN];   // eta-scaled k
__device__ float g_v[BATCH*SEQ*DIMN];
__device__ float g_q[BATCH*SEQ*DIMN];
__device__ float g_y[BATCH*SEQ*DIMN];   // memory_out
__device__ float g_dA[BATCH*NC*DIMN*DIMN];  // per-chunk state increments
__device__ float g_As[BATCH*NC*DIMN*DIMN];  // per-chunk prefix states

// ---------------- packed f32x2 helpers (Blackwell FFMA2) -------------------
typedef unsigned long long ull;

__device__ __forceinline__ ull pack2(float lo, float hi) {
    ull r; asm("mov.b64 %0,{%1,%2};" : "=l"(r) : "f"(lo), "f"(hi)); return r;
}
__device__ __forceinline__ void unpack2(ull p, float& lo, float& hi) {
    asm("mov.b64 {%0,%1},%2;" : "=f"(lo), "=f"(hi) : "l"(p));
}
__device__ __forceinline__ ull fma2(ull a, ull b, ull c) {
    ull d; asm("fma.rn.f32x2 %0,%1,%2,%3;" : "=l"(d) : "l"(a), "l"(b), "l"(c)); return d;
}

// ---------------- GEMM: C = alpha * (X @ W^T + bias) -----------------------
#define BM 128
#define BN 64
#define BK 16

__global__ __launch_bounds__(256, 2) void gemm_kernel(
    const float* __restrict__ Xin, const float* __restrict__ W,
    const float* __restrict__ bias, float* __restrict__ Cout,
    float alpha, int mode)
{
    const float* X = (mode == 3) ? g_y : Xin;
    float* C = (mode == 0) ? g_k : (mode == 1) ? g_v : (mode == 2) ? g_q : Cout;

    __shared__ __align__(16) float Xs[BK][BM];
    __shared__ __align__(16) float Ws[BK][BN];

    const int tid   = threadIdx.x;
    const int mBase = blockIdx.x * BM;
    const int nBase = blockIdx.y * BN;

    const int tx = tid & 15;
    const int ty = tid >> 4;
    const int m0 = ty * 8;
    const int n0 = tx * 4;

    ull acc[4][4];
#pragma unroll
    for (int i = 0; i < 4; i++)
#pragma unroll
        for (int j = 0; j < 4; j++) acc[i][j] = 0ull;

    const int xrow = tid & 127;
    const int xkq  = tid >> 7;
    const int wrow = tid & 63;
    const int wkq  = tid >> 6;

    for (int k0 = 0; k0 < DIMN; k0 += BK) {
        float4 xv0 = *(const float4*)(X + (size_t)(mBase + xrow) * DIMN + k0 + xkq * 4);
        float4 xv1 = *(const float4*)(X + (size_t)(mBase + xrow) * DIMN + k0 + (xkq + 2) * 4);
        float4 wv  = *(const float4*)(W + (size_t)(nBase + wrow) * DIMN + k0 + wkq * 4);

        __syncthreads();
        Xs[xkq * 4 + 0][xrow] = xv0.x;
        Xs[xkq * 4 + 1][xrow] = xv0.y;
        Xs[xkq * 4 + 2][xrow] = xv0.z;
        Xs[xkq * 4 + 3][xrow] = xv0.w;
        Xs[(xkq + 2) * 4 + 0][xrow] = xv1.x;
        Xs[(xkq + 2) * 4 + 1][xrow] = xv1.y;
        Xs[(xkq + 2) * 4 + 2][xrow] = xv1.z;
        Xs[(xkq + 2) * 4 + 3][xrow] = xv1.w;
        Ws[wkq * 4 + 0][wrow] = wv.x;
        Ws[wkq * 4 + 1][wrow] = wv.y;
        Ws[wkq * 4 + 2][wrow] = wv.z;
        Ws[wkq * 4 + 3][wrow] = wv.w;
        __syncthreads();

#pragma unroll
        for (int kk = 0; kk < BK; kk++) {
            ulonglong2 A0 = *(const ulonglong2*)&Xs[kk][m0];
            ulonglong2 A1 = *(const ulonglong2*)&Xs[kk][m0 + 4];
            float4 bv = *(const float4*)&Ws[kk][n0];
            ull ap[4] = { A0.x, A0.y, A1.x, A1.y };
            ull bp[4] = { pack2(bv.x, bv.x), pack2(bv.y, bv.y),
                          pack2(bv.z, bv.z), pack2(bv.w, bv.w) };
#pragma unroll
            for (int i = 0; i < 4; i++)
#pragma unroll
                for (int j = 0; j < 4; j++)
                    acc[i][j] = fma2(ap[i], bp[j], acc[i][j]);
        }
    }

    float4 bb = *(const float4*)(bias + nBase + n0);
    float bia[4] = { bb.x, bb.y, bb.z, bb.w };
#pragma unroll
    for (int i = 0; i < 4; i++) {
        float lo[4], hi[4];
#pragma unroll
        for (int j = 0; j < 4; j++) unpack2(acc[i][j], lo[j], hi[j]);
        float4 r0 = make_float4(alpha * (lo[0] + bia[0]), alpha * (lo[1] + bia[1]),
                                alpha * (lo[2] + bia[2]), alpha * (lo[3] + bia[3]));
        float4 r1 = make_float4(alpha * (hi[0] + bia[0]), alpha * (hi[1] + bia[1]),
                                alpha * (hi[2] + bia[2]), alpha * (hi[3] + bia[3]));
        *(float4*)(C + (size_t)(mBase + m0 + 2 * i)     * DIMN + nBase + n0) = r0;
        *(float4*)(C + (size_t)(mBase + m0 + 2 * i + 1) * DIMN + nBase + n0) = r1;
    }
}

// ---------------- attn_local: S = mask(lam^(i-j) eta q.k), Y_intra = S@V ----
// grid: B*NC = 512 CTAs, 256 threads. Chunk = 64 rows.
__global__ __launch_bounds__(256) void attn_local_kernel()
{
    const int b  = blockIdx.x >> 6;
    const int c  = blockIdx.x & 63;
    const int t0 = c * CH;
    const int tid = threadIdx.x;
    const int tx = tid & 15, ty = tid >> 4;
    const int i0 = ty * 4, j0 = tx * 4;

    __shared__ float Qt[64][64];   // [kk][i]  (phase2: reused as Vs[j][n])
    __shared__ float Kt[64][64];   // [kk][j]
    __shared__ float Ss[64][64];   // [j][i]

    // loader mapping: row = tid>>2, 4 float4 at cols (tid&3)*4 + u*16
    const int lrow = tid >> 2;
    const int lc4  = (tid & 3) * 4;

    const float qsc = powf(DECAYC, (float)lrow);
    const float ksc = powf(DECAYC, -(float)lrow);
    const size_t rowbase = ((size_t)(b * SEQ + t0 + lrow)) * DIMN;

    ull s2[2][4];
#pragma unroll
    for (int r = 0; r < 2; r++)
#pragma unroll
        for (int j = 0; j < 4; j++) s2[r][j] = 0ull;

    // ---- phase 1: S = scaled Q K^T over 4 k-tiles of 64 ----
    for (int kt = 0; kt < 4; kt++) {
        float4 qv[4], kv[4];
#pragma unroll
        for (int u = 0; u < 4; u++) {
            qv[u] = *(const float4*)(g_q + rowbase + kt * 64 + lc4 + u * 16);
            kv[u] = *(const float4*)(g_k + rowbase + kt * 64 + lc4 + u * 16);
        }
        __syncthreads();
#pragma unroll
        for (int u = 0; u < 4; u++) {
            const int col = lc4 + u * 16;
            Qt[col + 0][lrow] = qv[u].x * qsc;
            Qt[col + 1][lrow] = qv[u].y * qsc;
            Qt[col + 2][lrow] = qv[u].z * qsc;
            Qt[col + 3][lrow] = qv[u].w * qsc;
            Kt[col + 0][lrow] = kv[u].x * ksc;
            Kt[col + 1][lrow] = kv[u].y * ksc;
            Kt[col + 2][lrow] = kv[u].z * ksc;
            Kt[col + 3][lrow] = kv[u].w * ksc;
        }
        __syncthreads();
#pragma unroll
        for (int kk = 0; kk < 64; kk++) {
            float4 q4 = *(const float4*)&Qt[kk][i0];
            float4 k4 = *(const float4*)&Kt[kk][j0];
            ull qp0 = pack2(q4.x, q4.y);
            ull qp1 = pack2(q4.z, q4.w);
            ull kb[4] = { pack2(k4.x, k4.x), pack2(k4.y, k4.y),
                          pack2(k4.z, k4.z), pack2(k4.w, k4.w) };
#pragma unroll
            for (int j = 0; j < 4; j++) {
                s2[0][j] = fma2(qp0, kb[j], s2[0][j]);
                s2[1][j] = fma2(qp1, kb[j], s2[1][j]);
            }
        }
    }

    // masked write of S (layout [j][i] for phase-2 reads)
#pragma unroll
    for (int r = 0; r < 2; r++)
#pragma unroll
        for (int j = 0; j < 4; j++) {
            float lo, hi; unpack2(s2[r][j], lo, hi);
            const int ilo = i0 + 2 * r, ihi = ilo + 1, jc = j0 + j;
            Ss[jc][ilo] = (jc <= ilo) ? lo : 0.0f;
            Ss[jc][ihi] = (jc <= ihi) ? hi : 0.0f;
        }

    // ---- phase 2: Y_intra = S @ V (4 n-tiles of 64), Vs reuses Qt ----
    float (*Vs)[64] = Qt;
    const size_t ybase = ((size_t)(b * SEQ + t0)) * DIMN;
    for (int nt = 0; nt < 4; nt++) {
        float4 vv[4];
#pragma unroll
        for (int u = 0; u < 4; u++)
            vv[u] = *(const float4*)(g_v + rowbase + nt * 64 + lc4 + u * 16);
        __syncthreads();
#pragma unroll
        for (int u = 0; u < 4; u++)
            *(float4*)&Vs[lrow][lc4 + u * 16] = vv[u];
        __syncthreads();

        ull y2[4][2];
#pragma unroll
        for (int r = 0; r < 4; r++) { y2[r][0] = 0ull; y2[r][1] = 0ull; }
#pragma unroll
        for (int j = 0; j < 64; j++) {
            float4 s4 = *(const float4*)&Ss[j][i0];
            float4 v4 = *(const float4*)&Vs[j][tx * 4];
            ull vp0 = pack2(v4.x, v4.y), vp1 = pack2(v4.z, v4.w);
            float sr[4] = { s4.x, s4.y, s4.z, s4.w };
#pragma unroll
            for (int r = 0; r < 4; r++) {
                ull sb = pack2(sr[r], sr[r]);
                y2[r][0] = fma2(sb, vp0, y2[r][0]);
                y2[r][1] = fma2(sb, vp1, y2[r][1]);
            }
        }
#pragma unroll
        for (int r = 0; r < 4; r++) {
            float a, bb2, cc, dd;
            unpack2(y2[r][0], a, bb2);
            unpack2(y2[r][1], cc, dd);
            *(float4*)(g_y + ybase + (size_t)(i0 + r) * DIMN + nt * 64 + tx * 4)
                = make_float4(a, bb2, cc, dd);
        }
    }
}

// ---------------- dA kernel: dA = (eta lam^(C-1-j) K)^T @ V -----------------
// grid: B*NC*4 = 2048 CTAs (2x2 tiles of 128), 256 threads
__global__ __launch_bounds__(256) void dA_kernel()
{
    const int bid  = blockIdx.x;
    const int bc   = bid >> 2;
    const int tile = bid & 3;
    const int b = bc >> 6, c = bc & 63;
    const int t0  = c * CH;
    const int d1b = (tile & 1) * 128;
    const int d2b = (tile >> 1) * 128;

    __shared__ float Ks[32][128];
    __shared__ float Vs[32][128];

    const int tid = threadIdx.x;
    const int tx = tid & 15, ty = tid >> 4;

    // loader: row = tid>>3 (0..31), 4 float4 at cols (tid&7)*4 + u*32
    const int lrow = tid >> 3;
    const int lc4  = (tid & 7) * 4;

    ull acc[8][4];
#pragma unroll
    for (int r = 0; r < 8; r++)
#pragma unroll
        for (int p = 0; p < 4; p++) acc[r][p] = 0ull;

    for (int jt = 0; jt < 2; jt++) {
        const float ksc = powf(DECAYC, (float)(CH - 1 - (jt * 32 + lrow)));
        const size_t rbase = ((size_t)(b * SEQ + t0 + jt * 32 + lrow)) * DIMN;
        float4 kv[4], vv[4];
#pragma unroll
        for (int u = 0; u < 4; u++) {
            kv[u] = *(const float4*)(g_k + rbase + d1b + lc4 + u * 32);
            vv[u] = *(const float4*)(g_v + rbase + d2b + lc4 + u * 32);
        }
        __syncthreads();
#pragma unroll
        for (int u = 0; u < 4; u++) {
            const int col = lc4 + u * 32;
            Ks[lrow][col + 0] = kv[u].x * ksc;
            Ks[lrow][col + 1] = kv[u].y * ksc;
            Ks[lrow][col + 2] = kv[u].z * ksc;
            Ks[lrow][col + 3] = kv[u].w * ksc;
            *(float4*)&Vs[lrow][col] = vv[u];
        }
        __syncthreads();
#pragma unroll
        for (int j = 0; j < 32; j++) {
            float4 ka = *(const float4*)&Ks[j][ty * 8];
            float4 kb = *(const float4*)&Ks[j][ty * 8 + 4];
            float4 va = *(const float4*)&Vs[j][tx * 8];
            float4 vb = *(const float4*)&Vs[j][tx * 8 + 4];
            ull vp[4] = { pack2(va.x, va.y), pack2(va.z, va.w),
                          pack2(vb.x, vb.y), pack2(vb.z, vb.w) };
            float kr[8] = { ka.x, ka.y, ka.z, ka.w, kb.x, kb.y, kb.z, kb.w };
#pragma unroll
            for (int r = 0; r < 8; r++) {
                ull kd = pack2(kr[r], kr[r]);
#pragma unroll
                for (int p = 0; p < 4; p++)
                    acc[r][p] = fma2(kd, vp[p], acc[r][p]);
            }
        }
    }

    const size_t obase = ((size_t)(b * NC + c)) * DIMN * DIMN;
#pragma unroll
    for (int r = 0; r < 8; r++) {
        float f[8];
        unpack2(acc[r][0], f[0], f[1]);
        unpack2(acc[r][1], f[2], f[3]);
        unpack2(acc[r][2], f[4], f[5]);
        unpack2(acc[r][3], f[6], f[7]);
        float* p = g_dA + obase + (size_t)(d1b + ty * 8 + r) * DIMN + d2b + tx * 8;
        *(float4*)(p)     = make_float4(f[0], f[1], f[2], f[3]);
        *(float4*)(p + 4) = make_float4(f[4], f[5], f[6], f[7]);
    }
}

// ---------------- state combine: A_{c+1} = lam^C A_c + dA_c ------------------
// grid: B*D*D/256 = 2048 CTAs. Stores prefix state per chunk into g_As.
__global__ __launch_bounds__(256) void state_combine_kernel(
    const float* __restrict__ st_in, float* __restrict__ st_out)
{
    const int idx = blockIdx.x * 256 + threadIdx.x;
    const int b = idx >> 16;
    const int e = idx & 65535;
    float A = st_in[(size_t)b * 65536 + e];
    const float lc = 0.00117901845f;   // 0.9^64
    const size_t base = ((size_t)b * NC) * 65536 + e;
#pragma unroll 4
    for (int c = 0; c < NC; c++) {
        g_As[base + (size_t)c * 65536] = A;
        A = lc * A + g_dA[base + (size_t)c * 65536];
    }
    if (st_out) st_out[(size_t)b * 65536 + e] = A;
}

// ---------------- y_inter: Y += lam^(i+1) Q @ A_prev(chunk) ------------------
// grid: B*NC = 512 CTAs, 256 threads
__global__ __launch_bounds__(256) void y_inter_kernel()
{
    const int b  = blockIdx.x >> 6;
    const int c  = blockIdx.x & 63;
    const int t0 = c * CH;
    const int tid = threadIdx.x;
    const int tx = tid & 15, ty = tid >> 4;
    const int i0 = ty * 4, n0 = tx * 4;

    __shared__ float Qt[64][64];   // [kk][i]
    __shared__ float As[64][64];   // [kk][n]

    const int lrow = tid >> 2;
    const int lc4  = (tid & 3) * 4;
    const float qsc = powf(DECAYC, (float)(lrow + 1));
    const size_t qbase = ((size_t)(b * SEQ + t0 + lrow)) * DIMN;
    const size_t Abase = ((size_t)(b * NC + c)) * 65536;

    ull y2[4][8];
#pragma unroll
    for (int r = 0; r < 4; r++)
#pragma unroll
        for (int p = 0; p < 8; p++) y2[r][p] = 0ull;

    for (int kt = 0; kt < 4; kt++) {
        float4 qv[4];
#pragma unroll
        for (int u = 0; u < 4; u++)
            qv[u] = *(const float4*)(g_q + qbase + kt * 64 + lc4 + u * 16);
        __syncthreads();
#pragma unroll
        for (int u = 0; u < 4; u++) {
            const int col = lc4 + u * 16;
            Qt[col + 0][lrow] = qv[u].x * qsc;
            Qt[col + 1][lrow] = qv[u].y * qsc;
            Qt[col + 2][lrow] = qv[u].z * qsc;
            Qt[col + 3][lrow] = qv[u].w * qsc;
        }
        for (int nt = 0; nt < 4; nt++) {
            float4 av[4];
#pragma unroll
            for (int u = 0; u < 4; u++)
                av[u] = *(const float4*)(g_As + Abase +
                        (size_t)(kt * 64 + lrow) * DIMN + nt * 64 + lc4 + u * 16);
            __syncthreads();
#pragma unroll
            for (int u = 0; u < 4; u++)
                *(float4*)&As[lrow][lc4 + u * 16] = av[u];
            __syncthreads();
#pragma unroll
            for (int kk = 0; kk < 64; kk++) {
                float4 q4 = *(const float4*)&Qt[kk][i0];
                float4 a4 = *(const float4*)&As[kk][n0];
                ull ap0 = pack2(a4.x, a4.y), ap1 = pack2(a4.z, a4.w);
                float qr[4] = { q4.x, q4.y, q4.z, q4.w };
#pragma unroll
                for (int r = 0; r < 4; r++) {
                    ull qb = pack2(qr[r], qr[r]);
                    y2[r][nt * 2]     = fma2(qb, ap0, y2[r][nt * 2]);
                    y2[r][nt * 2 + 1] = fma2(qb, ap1, y2[r][nt * 2 + 1]);
                }
            }
        }
    }

    const size_t ybase = ((size_t)(b * SEQ + t0)) * DIMN;
#pragma unroll
    for (int r = 0; r < 4; r++)
#pragma unroll
        for (int nt = 0; nt < 4; nt++) {
            float a, bb2, cc, dd;
            unpack2(y2[r][nt * 2], a, bb2);
            unpack2(y2[r][nt * 2 + 1], cc, dd);
            float* p = g_y + ybase + (size_t)(i0 + r) * DIMN + nt * 64 + n0;
            float4 old = *(float4*)p;
            *(float4*)p = make_float4(old.x + a, old.y + bb2, old.z + cc, old.w + dd);
        }
}

// ---------------- launch ---------------------------------------------------
extern "C" void kernel_launch(void* const* d_in, const int* in_sizes, int n_in,
                              void* d_out, int out_size)
{
    const float* x  = (const float*)d_in[0];
    const float* st = (const float*)d_in[1];
    const float* Wk = (const float*)d_in[2];
    const float* bk = (const float*)d_in[3];
    const float* Wv = (const float*)d_in[4];
    const float* bv = (const float*)d_in[5];
    const float* Wq = (const float*)d_in[6];
    const float* bq = (const float*)d_in[7];
    const float* Wo = (const float*)d_in[8];
    const float* bo = (const float*)d_in[9];

    float* out = (float*)d_out;
    float* state_out = nullptr;
    const long long need = (long long)BATCH * SEQ * DIMN + (long long)BATCH * DIMN * DIMN;
    if ((long long)out_size >= need)
        state_out = out + (size_t)BATCH * SEQ * DIMN;

    dim3 grid(MTOT / BM, DIMN / BN);   // (256, 4)

    // projections (k pre-scaled by eta = LR, including its bias)
    gemm_kernel<<<grid, 256>>>(x, Wk, bk, nullptr, LRC, 0);
    gemm_kernel<<<grid, 256>>>(x, Wv, bv, nullptr, 1.0f, 1);
    gemm_kernel<<<grid, 256>>>(x, Wq, bq, nullptr, 1.0f, 2);

    // chunked scan path
    attn_local_kernel<<<BATCH * NC, 256>>>();            // Y_intra -> g_y
    dA_kernel<<<BATCH * NC * 4, 256>>>();                // dA per chunk
    state_combine_kernel<<<2048, 256>>>(st, state_out);  // prefix states -> g_As
    y_inter_kernel<<<BATCH * NC, 256>>>();               // g_y += Q @ A_prev

    // output projection
    gemm_kernel<<<grid, 256>>>(nullptr, Wo, bo, out, 1.0f, 3);
}

// round 4
// speedup vs baseline: 3.1486x; 1.3481x over previous
#include <cuda_runtime.h>
#include <cuda_bf16.h>
#include <cstdint>
#include <math.h>

#define DIMN   256
#define BATCH  8
#define SEQ    4096
#define LRC    0.1f
#define DECAYC 0.9f
#define MTOT   (BATCH*SEQ)          // 32768
#define CH     64                   // chunk length
#define NC     (SEQ/CH)             // 64 chunks

// ---------------- scratch (device globals: allocation-free) ----------------
__device__ float g_k[BATCH*SEQ*DIMN];   // eta-scaled k
__device__ float g_v[BATCH*SEQ*DIMN];
__device__ float g_q[BATCH*SEQ*DIMN];
__device__ float g_y[BATCH*SEQ*DIMN];   // memory_out
__device__ float g_dA[BATCH*NC*DIMN*DIMN];  // per-chunk state increments
__device__ float g_As[BATCH*NC*DIMN*DIMN];  // per-chunk prefix states

__device__ __nv_bfloat16 g_xhi[MTOT*DIMN];
__device__ __nv_bfloat16 g_xlo[MTOT*DIMN];
__device__ __nv_bfloat16 g_yhi[MTOT*DIMN];
__device__ __nv_bfloat16 g_ylo[MTOT*DIMN];
__device__ __nv_bfloat16 g_whi[4*DIMN*DIMN];
__device__ __nv_bfloat16 g_wlo[4*DIMN*DIMN];

// ---------------- packed f32x2 helpers (Blackwell FFMA2) -------------------
typedef unsigned long long ull;

__device__ __forceinline__ ull pack2(float lo, float hi) {
    ull r; asm("mov.b64 %0,{%1,%2};" : "=l"(r) : "f"(lo), "f"(hi)); return r;
}
__device__ __forceinline__ void unpack2(ull p, float& lo, float& hi) {
    asm("mov.b64 {%0,%1},%2;" : "=f"(lo), "=f"(hi) : "l"(p));
}
__device__ __forceinline__ ull fma2(ull a, ull b, ull c) {
    ull d; asm("fma.rn.f32x2 %0,%1,%2,%3;" : "=l"(d) : "l"(a), "l"(b), "l"(c)); return d;
}

// ---------------- split conversion: fp32 -> bf16 hi + bf16 lo --------------
__global__ __launch_bounds__(256) void conv_split_kernel(
    const float* __restrict__ in, __nv_bfloat16* __restrict__ hi,
    __nv_bfloat16* __restrict__ lo, int n4)
{
    int i = blockIdx.x * 256 + threadIdx.x;
    if (i >= n4) return;
    float4 v = ((const float4*)in)[i];
    __nv_bfloat16 h0 = __float2bfloat16(v.x);
    __nv_bfloat16 h1 = __float2bfloat16(v.y);
    __nv_bfloat16 h2 = __float2bfloat16(v.z);
    __nv_bfloat16 h3 = __float2bfloat16(v.w);
    __nv_bfloat16 l0 = __float2bfloat16(v.x - __bfloat162float(h0));
    __nv_bfloat16 l1 = __float2bfloat16(v.y - __bfloat162float(h1));
    __nv_bfloat16 l2 = __float2bfloat16(v.z - __bfloat162float(h2));
    __nv_bfloat16 l3 = __float2bfloat16(v.w - __bfloat162float(h3));
    __nv_bfloat162* hp = (__nv_bfloat162*)hi;
    __nv_bfloat162* lp = (__nv_bfloat162*)lo;
    hp[2 * i]     = __nv_bfloat162(h0, h1);
    hp[2 * i + 1] = __nv_bfloat162(h2, h3);
    lp[2 * i]     = __nv_bfloat162(l0, l1);
    lp[2 * i + 1] = __nv_bfloat162(l2, l3);
}

// ---------------- HMMA GEMM: C = alpha*(A @ W^T + bias) --------------------
// mma.sync.m16n8k16 row.col, bf16x3 compensated (hi*hi + hi*lo + lo*hi).
// A: (MTOT,256) bf16 hi/lo row-major. W: (256,256) bf16 hi/lo row-major [n][k]
// (exactly the col-major B operand layout). CTA 256 thr, tile 128(M)x128(N),
// K chunked 4x64. Warp tile 32x64 = 2(m) x 8(n) mma tiles.
#define ASTR 72                    // smem row stride (bf16) -> conflict-free
#define HG_SMEM (4 * 128 * ASTR * 2)   // 73728 bytes

__device__ __forceinline__ void mma16816(float* c, const uint32_t* a, const uint32_t* b) {
    asm volatile(
        "mma.sync.aligned.m16n8k16.row.col.f32.bf16.bf16.f32 "
        "{%0,%1,%2,%3}, {%4,%5,%6,%7}, {%8,%9}, {%0,%1,%2,%3};"
        : "+f"(c[0]), "+f"(c[1]), "+f"(c[2]), "+f"(c[3])
        : "r"(a[0]), "r"(a[1]), "r"(a[2]), "r"(a[3]), "r"(b[0]), "r"(b[1]));
}

__global__ __launch_bounds__(256, 1) void hmma_gemm_kernel(
    const __nv_bfloat16* __restrict__ Ahi, const __nv_bfloat16* __restrict__ Alo,
    const __nv_bfloat16* __restrict__ Whi, const __nv_bfloat16* __restrict__ Wlo,
    const float* __restrict__ bias, float* __restrict__ C, float alpha)
{
    extern __shared__ __align__(16) __nv_bfloat16 smem[];
    __nv_bfloat16* sAhi = smem;
    __nv_bfloat16* sAlo = smem + 128 * ASTR;
    __nv_bfloat16* sBhi = smem + 2 * 128 * ASTR;
    __nv_bfloat16* sBlo = smem + 3 * 128 * ASTR;

    const int tid  = threadIdx.x;
    const int wid  = tid >> 5;
    const int lane = tid & 31;
    const int gId  = lane >> 2;          // 0..7
    const int tig  = lane & 3;           // 0..3
    const int mBase = blockIdx.x * 128;
    const int nBase = blockIdx.y * 128;
    const int wm0 = (wid & 3) * 32;      // warp m offset in tile
    const int wn0 = (wid >> 2) * 64;     // warp n offset in tile

    float acc[2][8][4];
#pragma unroll
    for (int i = 0; i < 2; i++)
#pragma unroll
        for (int j = 0; j < 8; j++)
#pragma unroll
            for (int r = 0; r < 4; r++) acc[i][j][r] = 0.0f;

    const int lrow = tid >> 1;           // 0..127
    const int lhalf = tid & 1;           // 0..1  (32 bf16 halves of 64)

    for (int kc = 0; kc < 4; kc++) {
        __syncthreads();
        // load A chunk (rows mBase.., cols kc*64..) and W chunk (rows nBase..)
        {
            const size_t ga = (size_t)(mBase + lrow) * DIMN + kc * 64 + lhalf * 32;
            const size_t gb = (size_t)(nBase + lrow) * DIMN + kc * 64 + lhalf * 32;
            const uint4* pah = (const uint4*)(Ahi + ga);
            const uint4* pal = (const uint4*)(Alo + ga);
            const uint4* pbh = (const uint4*)(Whi + gb);
            const uint4* pbl = (const uint4*)(Wlo + gb);
            __nv_bfloat16* dA = sAhi + lrow * ASTR + lhalf * 32;
            __nv_bfloat16* dAl = sAlo + lrow * ASTR + lhalf * 32;
            __nv_bfloat16* dB = sBhi + lrow * ASTR + lhalf * 32;
            __nv_bfloat16* dBl = sBlo + lrow * ASTR + lhalf * 32;
#pragma unroll
            for (int u = 0; u < 4; u++) {
                *(uint4*)(dA + u * 8)  = pah[u];
                *(uint4*)(dAl + u * 8) = pal[u];
                *(uint4*)(dB + u * 8)  = pbh[u];
                *(uint4*)(dBl + u * 8) = pbl[u];
            }
        }
        __syncthreads();

#pragma unroll
        for (int kk = 0; kk < 4; kk++) {
            const int k0 = kk * 16 + tig * 2;
            uint32_t ah[2][4], al[2][4];
#pragma unroll
            for (int i = 0; i < 2; i++) {
                const int r0 = wm0 + i * 16 + gId;
                ah[i][0] = *(const uint32_t*)(sAhi + r0 * ASTR + k0);
                ah[i][1] = *(const uint32_t*)(sAhi + (r0 + 8) * ASTR + k0);
                ah[i][2] = *(const uint32_t*)(sAhi + r0 * ASTR + k0 + 8);
                ah[i][3] = *(const uint32_t*)(sAhi + (r0 + 8) * ASTR + k0 + 8);
                al[i][0] = *(const uint32_t*)(sAlo + r0 * ASTR + k0);
                al[i][1] = *(const uint32_t*)(sAlo + (r0 + 8) * ASTR + k0);
                al[i][2] = *(const uint32_t*)(sAlo + r0 * ASTR + k0 + 8);
                al[i][3] = *(const uint32_t*)(sAlo + (r0 + 8) * ASTR + k0 + 8);
            }
            uint32_t bh[8][2], bl[8][2];
#pragma unroll
            for (int j = 0; j < 8; j++) {
                const int nr = wn0 + j * 8 + gId;
                bh[j][0] = *(const uint32_t*)(sBhi + nr * ASTR + k0);
                bh[j][1] = *(const uint32_t*)(sBhi + nr * ASTR + k0 + 8);
                bl[j][0] = *(const uint32_t*)(sBlo + nr * ASTR + k0);
                bl[j][1] = *(const uint32_t*)(sBlo + nr * ASTR + k0 + 8);
            }
#pragma unroll
            for (int i = 0; i < 2; i++)
#pragma unroll
                for (int j = 0; j < 8; j++) {
                    mma16816(acc[i][j], ah[i], bh[j]);   // hi*hi
                    mma16816(acc[i][j], ah[i], bl[j]);   // hi*lo
                    mma16816(acc[i][j], al[i], bh[j]);   // lo*hi
                }
        }
    }

    // epilogue: D[row][col] mapping c0,c1 -> (gId, 2tig), c2,c3 -> (gId+8, 2tig)
#pragma unroll
    for (int i = 0; i < 2; i++) {
        const int r0 = mBase + wm0 + i * 16 + gId;
#pragma unroll
        for (int j = 0; j < 8; j++) {
            const int col = nBase + wn0 + j * 8 + tig * 2;
            const float b0 = bias[col], b1 = bias[col + 1];
            float2 o0 = make_float2(alpha * (acc[i][j][0] + b0),
                                    alpha * (acc[i][j][1] + b1));
            float2 o1 = make_float2(alpha * (acc[i][j][2] + b0),
                                    alpha * (acc[i][j][3] + b1));
            *(float2*)(C + (size_t)r0 * DIMN + col)       = o0;
            *(float2*)(C + (size_t)(r0 + 8) * DIMN + col) = o1;
        }
    }
}

// ---------------- attn_local: S = mask(lam^(i-j) eta q.k), Y_intra = S@V ----
__global__ __launch_bounds__(256) void attn_local_kernel()
{
    const int b  = blockIdx.x >> 6;
    const int c  = blockIdx.x & 63;
    const int t0 = c * CH;
    const int tid = threadIdx.x;
    const int tx = tid & 15, ty = tid >> 4;
    const int i0 = ty * 4, j0 = tx * 4;

    __shared__ float Qt[64][64];
    __shared__ float Kt[64][64];
    __shared__ float Ss[64][64];

    const int lrow = tid >> 2;
    const int lc4  = (tid & 3) * 4;

    const float qsc = powf(DECAYC, (float)lrow);
    const float ksc = powf(DECAYC, -(float)lrow);
    const size_t rowbase = ((size_t)(b * SEQ + t0 + lrow)) * DIMN;

    ull s2[2][4];
#pragma unroll
    for (int r = 0; r < 2; r++)
#pragma unroll
        for (int j = 0; j < 4; j++) s2[r][j] = 0ull;

    for (int kt = 0; kt < 4; kt++) {
        float4 qv[4], kv[4];
#pragma unroll
        for (int u = 0; u < 4; u++) {
            qv[u] = *(const float4*)(g_q + rowbase + kt * 64 + lc4 + u * 16);
            kv[u] = *(const float4*)(g_k + rowbase + kt * 64 + lc4 + u * 16);
        }
        __syncthreads();
#pragma unroll
        for (int u = 0; u < 4; u++) {
            const int col = lc4 + u * 16;
            Qt[col + 0][lrow] = qv[u].x * qsc;
            Qt[col + 1][lrow] = qv[u].y * qsc;
            Qt[col + 2][lrow] = qv[u].z * qsc;
            Qt[col + 3][lrow] = qv[u].w * qsc;
            Kt[col + 0][lrow] = kv[u].x * ksc;
            Kt[col + 1][lrow] = kv[u].y * ksc;
            Kt[col + 2][lrow] = kv[u].z * ksc;
            Kt[col + 3][lrow] = kv[u].w * ksc;
        }
        __syncthreads();
#pragma unroll
        for (int kk = 0; kk < 64; kk++) {
            float4 q4 = *(const float4*)&Qt[kk][i0];
            float4 k4 = *(const float4*)&Kt[kk][j0];
            ull qp0 = pack2(q4.x, q4.y);
            ull qp1 = pack2(q4.z, q4.w);
            ull kb[4] = { pack2(k4.x, k4.x), pack2(k4.y, k4.y),
                          pack2(k4.z, k4.z), pack2(k4.w, k4.w) };
#pragma unroll
            for (int j = 0; j < 4; j++) {
                s2[0][j] = fma2(qp0, kb[j], s2[0][j]);
                s2[1][j] = fma2(qp1, kb[j], s2[1][j]);
            }
        }
    }

#pragma unroll
    for (int r = 0; r < 2; r++)
#pragma unroll
        for (int j = 0; j < 4; j++) {
            float lo, hi; unpack2(s2[r][j], lo, hi);
            const int ilo = i0 + 2 * r, ihi = ilo + 1, jc = j0 + j;
            Ss[jc][ilo] = (jc <= ilo) ? lo : 0.0f;
            Ss[jc][ihi] = (jc <= ihi) ? hi : 0.0f;
        }

    float (*Vs)[64] = Qt;
    const size_t ybase = ((size_t)(b * SEQ + t0)) * DIMN;
    for (int nt = 0; nt < 4; nt++) {
        float4 vv[4];
#pragma unroll
        for (int u = 0; u < 4; u++)
            vv[u] = *(const float4*)(g_v + rowbase + nt * 64 + lc4 + u * 16);
        __syncthreads();
#pragma unroll
        for (int u = 0; u < 4; u++)
            *(float4*)&Vs[lrow][lc4 + u * 16] = vv[u];
        __syncthreads();

        ull y2[4][2];
#pragma unroll
        for (int r = 0; r < 4; r++) { y2[r][0] = 0ull; y2[r][1] = 0ull; }
#pragma unroll
        for (int j = 0; j < 64; j++) {
            float4 s4 = *(const float4*)&Ss[j][i0];
            float4 v4 = *(const float4*)&Vs[j][tx * 4];
            ull vp0 = pack2(v4.x, v4.y), vp1 = pack2(v4.z, v4.w);
            float sr[4] = { s4.x, s4.y, s4.z, s4.w };
#pragma unroll
            for (int r = 0; r < 4; r++) {
                ull sb2 = pack2(sr[r], sr[r]);
                y2[r][0] = fma2(sb2, vp0, y2[r][0]);
                y2[r][1] = fma2(sb2, vp1, y2[r][1]);
            }
        }
#pragma unroll
        for (int r = 0; r < 4; r++) {
            float a, bb2, cc, dd;
            unpack2(y2[r][0], a, bb2);
            unpack2(y2[r][1], cc, dd);
            *(float4*)(g_y + ybase + (size_t)(i0 + r) * DIMN + nt * 64 + tx * 4)
                = make_float4(a, bb2, cc, dd);
        }
    }
}

// ---------------- dA kernel: dA = (eta lam^(C-1-j) K)^T @ V -----------------
__global__ __launch_bounds__(256) void dA_kernel()
{
    const int bid  = blockIdx.x;
    const int bc   = bid >> 2;
    const int tile = bid & 3;
    const int b = bc >> 6, c = bc & 63;
    const int t0  = c * CH;
    const int d1b = (tile & 1) * 128;
    const int d2b = (tile >> 1) * 128;

    __shared__ float Ks[32][128];
    __shared__ float Vs[32][128];

    const int tid = threadIdx.x;
    const int tx = tid & 15, ty = tid >> 4;
    const int lrow = tid >> 3;
    const int lc4  = (tid & 7) * 4;

    ull acc[8][4];
#pragma unroll
    for (int r = 0; r < 8; r++)
#pragma unroll
        for (int p = 0; p < 4; p++) acc[r][p] = 0ull;

    for (int jt = 0; jt < 2; jt++) {
        const float ksc = powf(DECAYC, (float)(CH - 1 - (jt * 32 + lrow)));
        const size_t rbase = ((size_t)(b * SEQ + t0 + jt * 32 + lrow)) * DIMN;
        float4 kv[4], vv[4];
#pragma unroll
        for (int u = 0; u < 4; u++) {
            kv[u] = *(const float4*)(g_k + rbase + d1b + lc4 + u * 32);
            vv[u] = *(const float4*)(g_v + rbase + d2b + lc4 + u * 32);
        }
        __syncthreads();
#pragma unroll
        for (int u = 0; u < 4; u++) {
            const int col = lc4 + u * 32;
            Ks[lrow][col + 0] = kv[u].x * ksc;
            Ks[lrow][col + 1] = kv[u].y * ksc;
            Ks[lrow][col + 2] = kv[u].z * ksc;
            Ks[lrow][col + 3] = kv[u].w * ksc;
            *(float4*)&Vs[lrow][col] = vv[u];
        }
        __syncthreads();
#pragma unroll
        for (int j = 0; j < 32; j++) {
            float4 ka = *(const float4*)&Ks[j][ty * 8];
            float4 kb = *(const float4*)&Ks[j][ty * 8 + 4];
            float4 va = *(const float4*)&Vs[j][tx * 8];
            float4 vb = *(const float4*)&Vs[j][tx * 8 + 4];
            ull vp[4] = { pack2(va.x, va.y), pack2(va.z, va.w),
                          pack2(vb.x, vb.y), pack2(vb.z, vb.w) };
            float kr[8] = { ka.x, ka.y, ka.z, ka.w, kb.x, kb.y, kb.z, kb.w };
#pragma unroll
            for (int r = 0; r < 8; r++) {
                ull kd = pack2(kr[r], kr[r]);
#pragma unroll
                for (int p = 0; p < 4; p++)
                    acc[r][p] = fma2(kd, vp[p], acc[r][p]);
            }
        }
    }

    const size_t obase = ((size_t)(b * NC + c)) * DIMN * DIMN;
#pragma unroll
    for (int r = 0; r < 8; r++) {
        float f[8];
        unpack2(acc[r][0], f[0], f[1]);
        unpack2(acc[r][1], f[2], f[3]);
        unpack2(acc[r][2], f[4], f[5]);
        unpack2(acc[r][3], f[6], f[7]);
        float* p = g_dA + obase + (size_t)(d1b + ty * 8 + r) * DIMN + d2b + tx * 8;
        *(float4*)(p)     = make_float4(f[0], f[1], f[2], f[3]);
        *(float4*)(p + 4) = make_float4(f[4], f[5], f[6], f[7]);
    }
}

// ---------------- state combine: A_{c+1} = lam^C A_c + dA_c ------------------
__global__ __launch_bounds__(256) void state_combine_kernel(
    const float* __restrict__ st_in, float* __restrict__ st_out)
{
    const int idx = blockIdx.x * 256 + threadIdx.x;
    const int b = idx >> 16;
    const int e = idx & 65535;
    float A = st_in[(size_t)b * 65536 + e];
    const float lc = 0.00117901845f;   // 0.9^64
    const size_t base = ((size_t)b * NC) * 65536 + e;
#pragma unroll 4
    for (int c = 0; c < NC; c++) {
        g_As[base + (size_t)c * 65536] = A;
        A = lc * A + g_dA[base + (size_t)c * 65536];
    }
    if (st_out) st_out[(size_t)b * 65536 + e] = A;
}

// ---------------- y_inter: Y += lam^(i+1) Q @ A_prev(chunk) ------------------
__global__ __launch_bounds__(256) void y_inter_kernel()
{
    const int b  = blockIdx.x >> 6;
    const int c  = blockIdx.x & 63;
    const int t0 = c * CH;
    const int tid = threadIdx.x;
    const int tx = tid & 15, ty = tid >> 4;
    const int i0 = ty * 4, n0 = tx * 4;

    __shared__ float Qt[64][64];
    __shared__ float As[64][64];

    const int lrow = tid >> 2;
    const int lc4  = (tid & 3) * 4;
    const float qsc = powf(DECAYC, (float)(lrow + 1));
    const size_t qbase = ((size_t)(b * SEQ + t0 + lrow)) * DIMN;
    const size_t Abase = ((size_t)(b * NC + c)) * 65536;

    ull y2[4][8];
#pragma unroll
    for (int r = 0; r < 4; r++)
#pragma unroll
        for (int p = 0; p < 8; p++) y2[r][p] = 0ull;

    for (int kt = 0; kt < 4; kt++) {
        float4 qv[4];
#pragma unroll
        for (int u = 0; u < 4; u++)
            qv[u] = *(const float4*)(g_q + qbase + kt * 64 + lc4 + u * 16);
        __syncthreads();
#pragma unroll
        for (int u = 0; u < 4; u++) {
            const int col = lc4 + u * 16;
            Qt[col + 0][lrow] = qv[u].x * qsc;
            Qt[col + 1][lrow] = qv[u].y * qsc;
            Qt[col + 2][lrow] = qv[u].z * qsc;
            Qt[col + 3][lrow] = qv[u].w * qsc;
        }
        for (int nt = 0; nt < 4; nt++) {
            float4 av[4];
#pragma unroll
            for (int u = 0; u < 4; u++)
                av[u] = *(const float4*)(g_As + Abase +
                        (size_t)(kt * 64 + lrow) * DIMN + nt * 64 + lc4 + u * 16);
            __syncthreads();
#pragma unroll
            for (int u = 0; u < 4; u++)
                *(float4*)&As[lrow][lc4 + u * 16] = av[u];
            __syncthreads();
#pragma unroll
            for (int kk = 0; kk < 64; kk++) {
                float4 q4 = *(const float4*)&Qt[kk][i0];
                float4 a4 = *(const float4*)&As[kk][n0];
                ull ap0 = pack2(a4.x, a4.y), ap1 = pack2(a4.z, a4.w);
                float qr[4] = { q4.x, q4.y, q4.z, q4.w };
#pragma unroll
                for (int r = 0; r < 4; r++) {
                    ull qb = pack2(qr[r], qr[r]);
                    y2[r][nt * 2]     = fma2(qb, ap0, y2[r][nt * 2]);
                    y2[r][nt * 2 + 1] = fma2(qb, ap1, y2[r][nt * 2 + 1]);
                }
            }
        }
    }

    const size_t ybase = ((size_t)(b * SEQ + t0)) * DIMN;
#pragma unroll
    for (int r = 0; r < 4; r++)
#pragma unroll
        for (int nt = 0; nt < 4; nt++) {
            float a, bb2, cc, dd;
            unpack2(y2[r][nt * 2], a, bb2);
            unpack2(y2[r][nt * 2 + 1], cc, dd);
            float* p = g_y + ybase + (size_t)(i0 + r) * DIMN + nt * 64 + n0;
            float4 old = *(float4*)p;
            *(float4*)p = make_float4(old.x + a, old.y + bb2, old.z + cc, old.w + dd);
        }
}

// ---------------- launch ---------------------------------------------------
extern "C" void kernel_launch(void* const* d_in, const int* in_sizes, int n_in,
                              void* d_out, int out_size)
{
    const float* x  = (const float*)d_in[0];
    const float* st = (const float*)d_in[1];
    const float* Wk = (const float*)d_in[2];
    const float* bk = (const float*)d_in[3];
    const float* Wv = (const float*)d_in[4];
    const float* bv = (const float*)d_in[5];
    const float* Wq = (const float*)d_in[6];
    const float* bq = (const float*)d_in[7];
    const float* Wo = (const float*)d_in[8];
    const float* bo = (const float*)d_in[9];

    float* out = (float*)d_out;
    float* state_out = nullptr;
    const long long need = (long long)BATCH * SEQ * DIMN + (long long)BATCH * DIMN * DIMN;
    if ((long long)out_size >= need)
        state_out = out + (size_t)BATCH * SEQ * DIMN;

    void *p;
    cudaGetSymbolAddress(&p, g_k);   float* pk = (float*)p;
    cudaGetSymbolAddress(&p, g_v);   float* pv = (float*)p;
    cudaGetSymbolAddress(&p, g_q);   float* pq = (float*)p;
    cudaGetSymbolAddress(&p, g_y);   float* py = (float*)p;
    cudaGetSymbolAddress(&p, g_xhi); __nv_bfloat16* pxh = (__nv_bfloat16*)p;
    cudaGetSymbolAddress(&p, g_xlo); __nv_bfloat16* pxl = (__nv_bfloat16*)p;
    cudaGetSymbolAddress(&p, g_yhi); __nv_bfloat16* pyh = (__nv_bfloat16*)p;
    cudaGetSymbolAddress(&p, g_ylo); __nv_bfloat16* pyl = (__nv_bfloat16*)p;
    cudaGetSymbolAddress(&p, g_whi); __nv_bfloat16* pwh = (__nv_bfloat16*)p;
    cudaGetSymbolAddress(&p, g_wlo); __nv_bfloat16* pwl = (__nv_bfloat16*)p;

    cudaFuncSetAttribute(hmma_gemm_kernel,
                         cudaFuncAttributeMaxDynamicSharedMemorySize, HG_SMEM);

    const int WSZ = DIMN * DIMN;          // 65536
    const int XN4 = MTOT * DIMN / 4;      // 2097152

    // split conversions
    conv_split_kernel<<<(XN4 + 255) / 256, 256>>>(x, pxh, pxl, XN4);
    conv_split_kernel<<<WSZ / 4 / 256, 256>>>(Wk, pwh + 0 * WSZ, pwl + 0 * WSZ, WSZ / 4);
    conv_split_kernel<<<WSZ / 4 / 256, 256>>>(Wv, pwh + 1 * WSZ, pwl + 1 * WSZ, WSZ / 4);
    conv_split_kernel<<<WSZ / 4 / 256, 256>>>(Wq, pwh + 2 * WSZ, pwl + 2 * WSZ, WSZ / 4);
    conv_split_kernel<<<WSZ / 4 / 256, 256>>>(Wo, pwh + 3 * WSZ, pwl + 3 * WSZ, WSZ / 4);

    dim3 ggrid(MTOT / 128, 2);

    // projections (k pre-scaled by eta = LR, including its bias)
    hmma_gemm_kernel<<<ggrid, 256, HG_SMEM>>>(pxh, pxl, pwh + 0 * WSZ, pwl + 0 * WSZ, bk, pk, LRC);
    hmma_gemm_kernel<<<ggrid, 256, HG_SMEM>>>(pxh, pxl, pwh + 1 * WSZ, pwl + 1 * WSZ, bv, pv, 1.0f);
    hmma_gemm_kernel<<<ggrid, 256, HG_SMEM>>>(pxh, pxl, pwh + 2 * WSZ, pwl + 2 * WSZ, bq, pq, 1.0f);

    // chunked scan path
    attn_local_kernel<<<BATCH * NC, 256>>>();
    dA_kernel<<<BATCH * NC * 4, 256>>>();
    state_combine_kernel<<<2048, 256>>>(st, state_out);
    y_inter_kernel<<<BATCH * NC, 256>>>();

    // output projection
    conv_split_kernel<<<(XN4 + 255) / 256, 256>>>(py, pyh, pyl, XN4);
    hmma_gemm_kernel<<<ggrid, 256, HG_SMEM>>>(pyh, pyl, pwh + 3 * WSZ, pwl + 3 * WSZ, bo, out, 1.0f);
}